// round 4
// baseline (speedup 1.0000x reference)
#include <cuda_runtime.h>
#include <cstdint>

static constexpr int NG      = 16;
static constexpr int NPG     = 4096;
static constexpr int NN      = NG * NPG;     // 65536 nodes
static constexpr int EE      = 1048576;      // edges
static constexpr int H       = 32;           // hidden
static constexpr int FC1_IN  = NPG * H;      // 131072
static constexpr int FC1_OUT = 256;
static constexpr int FC2_OUT = 64;
static constexpr int FC1_BLOCKS = FC1_IN / 256;   // 512

// -------- scratch (device globals; no allocation allowed) --------
__device__ int   g_degi[NN];
__device__ int   g_cnt [NN];
__device__ int   g_off [NN];          // block-local exclusive offsets
__device__ int   g_bsum[256];         // per-256-node-block bases (after scan2)
__device__ float g_dinv[NN];
__device__ int   g_eidx[EE];          // CSR: src indices grouped by dst
__device__ float g_h0 [NN * H];
__device__ float g_h1 [NN * H];
__device__ float g_act[NN * H];       // final pre-activated features for fc1
__device__ float g_t1p[FC1_BLOCKS * NG * FC1_OUT];   // fc1 partials (8 MB)
__device__ float g_t1 [NG * FC1_OUT];
__device__ int   g_is64;

// ---- packed f32x2 helpers (sm_103a) ----
__device__ __forceinline__ void fma2(unsigned long long& d,
                                     unsigned long long a,
                                     unsigned long long b) {
    asm("fma.rn.f32x2 %0, %1, %2, %0;" : "+l"(d) : "l"(a), "l"(b));
}
__device__ __forceinline__ unsigned long long pack2(float lo, float hi) {
    unsigned long long r;
    asm("mov.b64 %0, {%1, %2};" : "=l"(r) : "f"(lo), "f"(hi));
    return r;
}
__device__ __forceinline__ float unpack_sum(unsigned long long v) {
    float lo, hi;
    asm("mov.b64 {%0, %1}, %2;" : "=f"(lo), "=f"(hi) : "l"(v));
    return lo + hi;
}

// -------- zero + parallel dtype detect (block 0) --------
// int64 edge buffers have all odd 32-bit words == 0 (values < 2^31).
__global__ void zero_detect_kernel(const unsigned int* __restrict__ w) {
    int t = threadIdx.x;
    int i = blockIdx.x * 256 + t;
    g_degi[i] = 0;
    g_cnt[i]  = 0;
    if (blockIdx.x == 0) {
        int ok  = (w[2 * t + 1] == 0u);
        int all = __syncthreads_and(ok);
        if (t == 0) g_is64 = all;
    }
}

__global__ void deg_kernel(const void* __restrict__ eiraw) {
    int e = blockIdx.x * blockDim.x + threadIdx.x;
    if (e >= EE) return;
    int d;
    if (g_is64) d = (int)((const long long*)eiraw)[EE + e];
    else        d = ((const int*)eiraw)[EE + e];
    atomicAdd(&g_degi[d], 1);
}

// -------- shfl-based scans --------
// scan1: per-256-block exclusive scan of degrees; emits dinv and block totals
__global__ void scan1_kernel() {
    __shared__ int wsum[8];
    int t = threadIdx.x, lane = t & 31, wp = t >> 5;
    int i = blockIdx.x * 256 + t;
    int v = g_degi[i];
    g_dinv[i] = rsqrtf((float)v + 1.0f);
    int s = v;
#pragma unroll
    for (int off = 1; off < 32; off <<= 1) {
        int x = __shfl_up_sync(0xffffffffu, s, off);
        if (lane >= off) s += x;
    }
    if (lane == 31) wsum[wp] = s;
    __syncthreads();
    if (wp == 0) {
        int orig = (lane < 8) ? wsum[lane] : 0;
        int ws = orig;
#pragma unroll
        for (int off = 1; off < 8; off <<= 1) {
            int x = __shfl_up_sync(0xffffffffu, ws, off);
            if (lane >= off) ws += x;
        }
        if (lane < 8) wsum[lane] = ws - orig;   // exclusive warp bases
    }
    __syncthreads();
    g_off[i] = s - v + wsum[wp];                 // block-local exclusive
    if (t == 255) g_bsum[blockIdx.x] = s + wsum[7];   // block total
}

// scan2: single block, exclusive scan of 256 block totals (in place)
__global__ void scan2_kernel() {
    __shared__ int wsum[8];
    int t = threadIdx.x, lane = t & 31, wp = t >> 5;
    int v = g_bsum[t];
    int s = v;
#pragma unroll
    for (int off = 1; off < 32; off <<= 1) {
        int x = __shfl_up_sync(0xffffffffu, s, off);
        if (lane >= off) s += x;
    }
    if (lane == 31) wsum[wp] = s;
    __syncthreads();
    if (wp == 0) {
        int orig = (lane < 8) ? wsum[lane] : 0;
        int ws = orig;
#pragma unroll
        for (int off = 1; off < 8; off <<= 1) {
            int x = __shfl_up_sync(0xffffffffu, ws, off);
            if (lane >= off) ws += x;
        }
        if (lane < 8) wsum[lane] = ws - orig;
    }
    __syncthreads();
    g_bsum[t] = s - v + wsum[wp];                // exclusive block base
}

// -------- merged: CSR fill (blocks < EE/256) + layer-1 transform ----------
__global__ void fill_transform_kernel(const void* __restrict__ eiraw,
                                      const float* __restrict__ in_x,
                                      const float* __restrict__ W) {
    int bid = blockIdx.x;
    if (bid < EE / 256) {
        int e = bid * 256 + threadIdx.x;
        int s, d;
        if (g_is64) {
            const long long* p = (const long long*)eiraw;
            s = (int)p[e];
            d = (int)p[EE + e];
        } else {
            const int* p = (const int*)eiraw;
            s = p[e];
            d = p[EE + e];
        }
        int pos = g_off[d] + g_bsum[d >> 8] + atomicAdd(&g_cnt[d], 1);
        g_eidx[pos] = s;
    } else {
        __shared__ float Ws[16 * 32];
        int tid = threadIdx.x;
        for (int i = tid; i < 16 * 32; i += 256) Ws[i] = W[i];
        __syncthreads();
        int warp = tid >> 5, lane = tid & 31;
        int n = (bid - EE / 256) * 8 + warp;
        float a = (lane < 16) ? in_x[n * 16 + lane] : 0.0f;
        float o = 0.0f;
#pragma unroll
        for (int k = 0; k < 16; k++)
            o = fmaf(__shfl_sync(0xffffffffu, a, k), Ws[k * 32 + lane], o);
        g_h0[n * 32 + lane] = o * g_dinv[n];
    }
}

// -------- fused CSR aggregation + activation (+ next matmul) --------
// LAYER 0: in g_h0, out g_h1, fused matmul (mid layer)
// LAYER 1: in g_h1, out g_h0, fused matmul (mid layer)
// LAYER 2: in g_h0, out g_act, activation only (feeds fc1)
template<int LAYER>
__global__ void agg_kernel(const float* __restrict__ W,
                           const float* __restrict__ b) {
    const float* hs_in = (LAYER == 1) ? g_h1 : g_h0;
    float* out = (LAYER == 0) ? g_h1 : (LAYER == 1) ? g_h0 : g_act;

    __shared__ float Ws[H * H];
    int tid = threadIdx.x;
    if (LAYER < 2) {
        for (int i = tid; i < H * H; i += 256) Ws[i] = W[i];
        __syncthreads();
    }
    int warp = tid >> 5, lane = tid & 31;
    int n = blockIdx.x * 8 + warp;
    int start = g_off[n] + g_bsum[n >> 8];
    int end   = start + g_degi[n];
    const float* hp = hs_in + lane;
    float acc0 = hs_in[n * H + lane];   // self-loop term
    float acc1 = 0.f, acc2 = 0.f, acc3 = 0.f;
    for (int e0 = start; e0 < end; e0 += 32) {
        int cnt = min(32, end - e0);
        int my  = (lane < cnt) ? g_eidx[e0 + lane] : 0;
        int j = 0;
        for (; j + 4 <= cnt; j += 4) {
            int s0 = __shfl_sync(0xffffffffu, my, j);
            int s1 = __shfl_sync(0xffffffffu, my, j + 1);
            int s2 = __shfl_sync(0xffffffffu, my, j + 2);
            int s3 = __shfl_sync(0xffffffffu, my, j + 3);
            float v0 = hp[s0 * H], v1 = hp[s1 * H];
            float v2 = hp[s2 * H], v3 = hp[s3 * H];
            acc0 += v0; acc1 += v1; acc2 += v2; acc3 += v3;
        }
        for (; j < cnt; j++) {
            int s = __shfl_sync(0xffffffffu, my, j);
            acc0 += hp[s * H];
        }
    }
    float dv = g_dinv[n];
    float a = fmaxf(dv * ((acc0 + acc1) + (acc2 + acc3)) + b[lane], 0.0f);
    if (LAYER == 2) { out[n * H + lane] = a; return; }
    float o = 0.0f;
#pragma unroll
    for (int k = 0; k < H; k++)
        o = fmaf(__shfl_sync(0xffffffffu, a, k), Ws[k * H + lane], o);
    out[n * H + lane] = o * dv;
}

// -------- fc1: per-block partials, packed f32x2 inner product ------------
__global__ void fc1_kernel(const float* __restrict__ fc1_w) {
    constexpr int CHUNK = 256;
    __shared__ float a_s[NG * CHUNK];            // 16 KB, [g][i]
    int t  = threadIdx.x;                         // output column 0..255
    int i0 = blockIdx.x * CHUNK;

    for (int idx = t; idx < NG * (CHUNK / 4); idx += 256) {
        int g  = idx >> 6;                        // / (CHUNK/4)
        int i4 = idx & (CHUNK / 4 - 1);
        float4 v = *reinterpret_cast<const float4*>(g_act + g * FC1_IN + i0 + i4 * 4);
        *reinterpret_cast<float4*>(&a_s[g * CHUNK + i4 * 4]) = v;
    }
    __syncthreads();

    unsigned long long r2[NG];
#pragma unroll
    for (int g = 0; g < NG; g++) r2[g] = 0ull;

    for (int i = 0; i < CHUNK; i += 4) {
        long base = (long)(i0 + i) * FC1_OUT + t;
        float w0 = fc1_w[base];
        float w1 = fc1_w[base + FC1_OUT];
        float w2 = fc1_w[base + 2 * FC1_OUT];
        float w3 = fc1_w[base + 3 * FC1_OUT];
        unsigned long long wA = pack2(w0, w1);
        unsigned long long wB = pack2(w2, w3);
#pragma unroll
        for (int g = 0; g < NG; g++) {
            unsigned long long aA =
                *reinterpret_cast<const unsigned long long*>(&a_s[g * CHUNK + i]);
            unsigned long long aB =
                *reinterpret_cast<const unsigned long long*>(&a_s[g * CHUNK + i + 2]);
            fma2(r2[g], aA, wA);
            fma2(r2[g], aB, wB);
        }
    }
    float* outp = g_t1p + blockIdx.x * (NG * FC1_OUT);
#pragma unroll
    for (int g = 0; g < NG; g++)
        outp[g * FC1_OUT + t] = unpack_sum(r2[g]);
}

// -------- reduce fc1 partials: g_t1[o] = sum over 512 blocks -------------
__global__ void reduce_t1_kernel() {
    int o = blockIdx.x * 256 + threadIdx.x;       // 16 blocks x 256
    float s0 = 0.f, s1 = 0.f, s2 = 0.f, s3 = 0.f;
    const float* p = g_t1p + o;
#pragma unroll 4
    for (int b = 0; b < FC1_BLOCKS; b += 4) {
        s0 += p[(b + 0) * (NG * FC1_OUT)];
        s1 += p[(b + 1) * (NG * FC1_OUT)];
        s2 += p[(b + 2) * (NG * FC1_OUT)];
        s3 += p[(b + 3) * (NG * FC1_OUT)];
    }
    g_t1[o] = (s0 + s1) + (s2 + s3);
}

// -------- fc2: out = relu(t1 + fc1_b) @ fc2_w + fc2_b, single block ------
__global__ void fc2_kernel(const float* __restrict__ fc1_b,
                           const float* __restrict__ fc2_w,
                           const float* __restrict__ fc2_b,
                           float* __restrict__ out) {
    __shared__ float s[NG * FC1_OUT];             // 16 KB
    int t = threadIdx.x;                           // 0..1023
    for (int idx = t; idx < NG * FC1_OUT; idx += 1024) {
        int k = idx & (FC1_OUT - 1);
        s[idx] = fmaxf(g_t1[idx] + fc1_b[k], 0.0f);
    }
    __syncthreads();
    int g = t >> 6, o = t & 63;
    float acc = fc2_b[o];
#pragma unroll 8
    for (int k = 0; k < FC1_OUT; k++)
        acc = fmaf(s[g * FC1_OUT + k], fc2_w[k * FC2_OUT + o], acc);
    out[g * FC2_OUT + o] = acc;
}

extern "C" void kernel_launch(void* const* d_in, const int* in_sizes, int n_in,
                              void* d_out, int out_size) {
    const float* x     = (const float*)d_in[0];
    const void*  ei    = d_in[1];
    const float* W1    = (const float*)d_in[2];
    const float* b1    = (const float*)d_in[3];
    const float* W2    = (const float*)d_in[4];
    const float* b2    = (const float*)d_in[5];
    const float* W3    = (const float*)d_in[6];
    const float* b3    = (const float*)d_in[7];
    const float* fc1_w = (const float*)d_in[8];
    const float* fc1_b = (const float*)d_in[9];
    const float* fc2_w = (const float*)d_in[10];
    const float* fc2_b = (const float*)d_in[11];
    float* out = (float*)d_out;

    zero_detect_kernel<<<NN / 256, 256>>>((const unsigned int*)ei);
    deg_kernel<<<EE / 256, 256>>>(ei);
    scan1_kernel<<<256, 256>>>();
    scan2_kernel<<<1, 256>>>();
    fill_transform_kernel<<<EE / 256 + NN / 8, 256>>>(ei, x, W1);

    agg_kernel<0><<<NN / 8, 256>>>(W2, b1);
    agg_kernel<1><<<NN / 8, 256>>>(W3, b2);
    agg_kernel<2><<<NN / 8, 256>>>(nullptr, b3);

    fc1_kernel<<<FC1_BLOCKS, 256>>>(fc1_w);
    reduce_t1_kernel<<<NG * FC1_OUT / 256, 256>>>();
    fc2_kernel<<<1, 1024>>>(fc1_b, fc2_w, fc2_b, out);
}

// round 7
// speedup vs baseline: 1.0417x; 1.0417x over previous
#include <cuda_runtime.h>
#include <cstdint>

static constexpr int NG      = 16;
static constexpr int NPG     = 4096;
static constexpr int NN      = NG * NPG;     // 65536 nodes
static constexpr int EE      = 1048576;      // edges
static constexpr int H       = 32;           // hidden
static constexpr int FC1_IN  = NPG * H;      // 131072
static constexpr int FC1_OUT = 256;
static constexpr int FC2_OUT = 64;
static constexpr int FC1_BLOCKS = 512;       // fc1 chunks of 256 inputs

static constexpr int NB = 592;               // 148 x 4 blocks, co-resident
static constexpr int NT = 256;
static constexpr int NWARP = NB * 8;         // 4736 warps

// -------- scratch (device globals; no allocation allowed) --------
// g_degi / g_cnt rely on being zero at kernel entry: zero at module load,
// and re-zeroed at the END of every run (phase P7), keeping the invariant.
__device__ int   g_degi[NN];
__device__ int   g_cnt [NN];
__device__ int   g_off [NN];          // block-local exclusive offsets
__device__ int   g_bsum[256];         // per-256-node-chunk bases (after scan2)
__device__ float g_dinv[NN];
__device__ int   g_eidx[EE];          // CSR: src indices grouped by dst
__device__ float g_h0 [NN * H];
__device__ float g_h1 [NN * H];
__device__ float g_act[NN * H];       // final pre-activated features for fc1
__device__ float g_t1p[FC1_BLOCKS * NG * FC1_OUT];   // fc1 partials (8 MB)
__device__ float g_t1 [NG * FC1_OUT];

// -------- software grid barrier (CG-style: bar.sync + release/acquire) ---
__device__ unsigned          g_bar_count;    // 0 at entry and after each use
__device__ volatile unsigned g_bar_gen;      // monotonically increasing

__device__ __forceinline__ void grid_sync() {
    __syncthreads();
    if (threadIdx.x == 0) {
        unsigned gen = g_bar_gen;
        __threadfence();                      // release (+ L1 invalidate via CCTL.IVALL)
        unsigned old = atomicAdd(&g_bar_count, 1u);
        if (old == (unsigned)NB - 1u) {
            g_bar_count = 0u;
            __threadfence();
            g_bar_gen = gen + 1u;             // release
        } else {
            while (g_bar_gen == gen) __nanosleep(64);
            __threadfence();                  // acquire
        }
    }
    __syncthreads();
}

// ---- packed f32x2 helpers (sm_103a) ----
__device__ __forceinline__ void fma2(unsigned long long& d,
                                     unsigned long long a,
                                     unsigned long long b) {
    asm("fma.rn.f32x2 %0, %1, %2, %0;" : "+l"(d) : "l"(a), "l"(b));
}
__device__ __forceinline__ unsigned long long pack2(float lo, float hi) {
    unsigned long long r;
    asm("mov.b64 %0, {%1, %2};" : "=l"(r) : "f"(lo), "f"(hi));
    return r;
}
__device__ __forceinline__ float unpack_sum(unsigned long long v) {
    float lo, hi;
    asm("mov.b64 {%0, %1}, %2;" : "=f"(lo), "=f"(hi) : "l"(v));
    return lo + hi;
}

// -------- fused CSR aggregation + activation (+ next matmul) phase -------
// LAYER 0: in g_h0, out g_h1, fused matmul
// LAYER 1: in g_h1, out g_h0, fused matmul
// LAYER 2: in g_h0, out g_act, activation only (feeds fc1)
template<int LAYER>
__device__ __forceinline__ void agg_phase(const float* __restrict__ W,
                                          const float* __restrict__ b,
                                          float* sh, int bid, int t) {
    const float* hs_in = (LAYER == 1) ? g_h1 : g_h0;
    float* outp = (LAYER == 0) ? g_h1 : (LAYER == 1) ? g_h0 : g_act;
    if (LAYER < 2)
        for (int i = t; i < H * H; i += NT) sh[i] = W[i];
    __syncthreads();
    int lane = t & 31, wp = t >> 5;
    float bl = b[lane];
    const float* hp = hs_in + lane;
    for (int n = bid * 8 + wp; n < NN; n += NWARP) {
        int start = g_off[n] + g_bsum[n >> 8];
        int end   = start + g_degi[n];
        float a0 = hs_in[n * H + lane];   // self-loop term
        float a1 = 0.f, a2 = 0.f, a3 = 0.f, a4 = 0.f, a5 = 0.f, a6 = 0.f, a7 = 0.f;
        for (int e0 = start; e0 < end; e0 += 32) {
            int cnt = min(32, end - e0);
            int my  = (lane < cnt) ? g_eidx[e0 + lane] : 0;
            int j = 0;
            for (; j + 8 <= cnt; j += 8) {
                int s0 = __shfl_sync(~0u, my, j);
                int s1 = __shfl_sync(~0u, my, j + 1);
                int s2 = __shfl_sync(~0u, my, j + 2);
                int s3 = __shfl_sync(~0u, my, j + 3);
                int s4 = __shfl_sync(~0u, my, j + 4);
                int s5 = __shfl_sync(~0u, my, j + 5);
                int s6 = __shfl_sync(~0u, my, j + 6);
                int s7 = __shfl_sync(~0u, my, j + 7);
                a0 += hp[s0 * H]; a1 += hp[s1 * H];
                a2 += hp[s2 * H]; a3 += hp[s3 * H];
                a4 += hp[s4 * H]; a5 += hp[s5 * H];
                a6 += hp[s6 * H]; a7 += hp[s7 * H];
            }
            for (; j < cnt; j++)
                a0 += hp[__shfl_sync(~0u, my, j) * H];
        }
        float dv = g_dinv[n];
        float agg = ((a0 + a1) + (a2 + a3)) + ((a4 + a5) + (a6 + a7));
        float a = fmaxf(dv * agg + bl, 0.0f);
        if (LAYER == 2) { outp[n * H + lane] = a; continue; }
        float o = 0.0f;
#pragma unroll
        for (int k = 0; k < H; k++)
            o = fmaf(__shfl_sync(~0u, a, k), sh[k * H + lane], o);
        outp[n * H + lane] = o * dv;
    }
}

__global__ __launch_bounds__(NT, 4)
void mega_kernel(const void* __restrict__ ei,
                 const float* __restrict__ x,
                 const float* __restrict__ W1, const float* __restrict__ b1,
                 const float* __restrict__ W2, const float* __restrict__ b2,
                 const float* __restrict__ W3, const float* __restrict__ b3,
                 const float* __restrict__ fc1_w, const float* __restrict__ fc1_b,
                 const float* __restrict__ fc2_w, const float* __restrict__ fc2_b,
                 float* __restrict__ out) {
    __shared__ float sh[NG * 256];      // 16 KB, reused per phase
    __shared__ int   shi[8];

    const int t = threadIdx.x, bid = blockIdx.x;
    const int lane = t & 31, wp = t >> 5;

    // dtype detect, per block (int64 buffers: odd 32-bit words all zero)
    const unsigned* w32 = (const unsigned*)ei;
    const int is64 = __syncthreads_and(w32[2 * t + 1] == 0u);

    // ---- P0: degree histogram (counters pre-zeroed invariant) ----
    if (is64) {
        const long long* p = (const long long*)ei + EE;
        for (int e = bid * NT + t; e < EE; e += NB * NT)
            atomicAdd(&g_degi[(int)p[e]], 1);
    } else {
        const int* p = (const int*)ei + EE;
        for (int e = bid * NT + t; e < EE; e += NB * NT)
            atomicAdd(&g_degi[p[e]], 1);
    }
    grid_sync();

    // ---- P1: per-256-chunk exclusive scan; emits dinv + chunk totals ----
    if (bid < 256) {
        int i = bid * 256 + t;
        int v = g_degi[i];
        g_dinv[i] = rsqrtf((float)v + 1.0f);
        int s = v;
#pragma unroll
        for (int off = 1; off < 32; off <<= 1) {
            int xx = __shfl_up_sync(~0u, s, off);
            if (lane >= off) s += xx;
        }
        if (lane == 31) shi[wp] = s;
        __syncthreads();
        if (wp == 0) {
            int orig = (lane < 8) ? shi[lane] : 0;
            int ws = orig;
#pragma unroll
            for (int off = 1; off < 8; off <<= 1) {
                int xx = __shfl_up_sync(~0u, ws, off);
                if (lane >= off) ws += xx;
            }
            if (lane < 8) shi[lane] = ws - orig;
        }
        __syncthreads();
        g_off[i] = s - v + shi[wp];
        if (t == 255) g_bsum[bid] = s + shi[7];
    }
    grid_sync();

    // ---- P2: exclusive scan of 256 chunk totals (block 0) ----
    if (bid == 0) {
        int v = g_bsum[t];
        int s = v;
#pragma unroll
        for (int off = 1; off < 32; off <<= 1) {
            int xx = __shfl_up_sync(~0u, s, off);
            if (lane >= off) s += xx;
        }
        if (lane == 31) shi[wp] = s;
        __syncthreads();
        if (wp == 0) {
            int orig = (lane < 8) ? shi[lane] : 0;
            int ws = orig;
#pragma unroll
            for (int off = 1; off < 8; off <<= 1) {
                int xx = __shfl_up_sync(~0u, ws, off);
                if (lane >= off) ws += xx;
            }
            if (lane < 8) shi[lane] = ws - orig;
        }
        __syncthreads();
        g_bsum[t] = s - v + shi[wp];
    }
    grid_sync();

    // ---- P3: CSR fill + layer-1 transform ----
    {
        // FIX (round-6 bug): load ALL 512 W1 entries, not just first 256.
        for (int i = t; i < 16 * 32; i += NT) sh[i] = W1[i];
        __syncthreads();
        if (is64) {
            const long long* p = (const long long*)ei;
            for (int e = bid * NT + t; e < EE; e += NB * NT) {
                int s = (int)p[e];
                int d = (int)p[EE + e];
                g_eidx[g_off[d] + g_bsum[d >> 8] + atomicAdd(&g_cnt[d], 1)] = s;
            }
        } else {
            const int* p = (const int*)ei;
            for (int e = bid * NT + t; e < EE; e += NB * NT) {
                int s = p[e];
                int d = p[EE + e];
                g_eidx[g_off[d] + g_bsum[d >> 8] + atomicAdd(&g_cnt[d], 1)] = s;
            }
        }
        for (int n = bid * 8 + wp; n < NN; n += NWARP) {
            float a = (lane < 16) ? x[n * 16 + lane] : 0.0f;
            float o = 0.0f;
#pragma unroll
            for (int k = 0; k < 16; k++)
                o = fmaf(__shfl_sync(~0u, a, k), sh[k * 32 + lane], o);
            g_h0[n * 32 + lane] = o * g_dinv[n];
        }
    }
    grid_sync();

    // ---- P4..P6: three aggregation layers ----
    agg_phase<0>(W2, b1, sh, bid, t);
    grid_sync();
    agg_phase<1>(W3, b2, sh, bid, t);
    grid_sync();
    agg_phase<2>(nullptr, b3, sh, bid, t);
    grid_sync();

    // ---- P7: fc1 partials (blocks 0..511) + restore counter invariant ----
    if (bid < FC1_BLOCKS) {
        int i0 = bid * 256;
        for (int idx = t; idx < NG * 64; idx += NT) {   // 16g x 64 float4
            int g  = idx >> 6;
            int i4 = idx & 63;
            float4 v = *reinterpret_cast<const float4*>(g_act + g * FC1_IN + i0 + i4 * 4);
            *reinterpret_cast<float4*>(&sh[g * 256 + i4 * 4]) = v;
        }
        __syncthreads();
        unsigned long long r2[NG];
#pragma unroll
        for (int g = 0; g < NG; g++) r2[g] = 0ull;
        for (int i = 0; i < 256; i += 4) {
            int base = (i0 + i) * FC1_OUT + t;
            unsigned long long wA = pack2(fc1_w[base],               fc1_w[base +     FC1_OUT]);
            unsigned long long wB = pack2(fc1_w[base + 2 * FC1_OUT], fc1_w[base + 3 * FC1_OUT]);
#pragma unroll
            for (int g = 0; g < NG; g++) {
                unsigned long long aA =
                    *reinterpret_cast<const unsigned long long*>(&sh[g * 256 + i]);
                unsigned long long aB =
                    *reinterpret_cast<const unsigned long long*>(&sh[g * 256 + i + 2]);
                fma2(r2[g], aA, wA);
                fma2(r2[g], aB, wB);
            }
        }
        float* outp = g_t1p + bid * (NG * FC1_OUT);
#pragma unroll
        for (int g = 0; g < NG; g++)
            outp[g * FC1_OUT + t] = unpack_sum(r2[g]);
    }
    for (int i = bid * NT + t; i < NN; i += NB * NT) {
        g_cnt[i]  = 0;
        g_degi[i] = 0;
    }
    grid_sync();

    // ---- P8: reduce fc1 partials (16 blocks of work) ----
    for (int o = bid * NT + t; o < NG * FC1_OUT; o += NB * NT) {
        float s0 = 0.f, s1 = 0.f, s2 = 0.f, s3 = 0.f;
        const float* p = g_t1p + o;
#pragma unroll 4
        for (int b = 0; b < FC1_BLOCKS; b += 4) {
            s0 += p[(b + 0) * (NG * FC1_OUT)];
            s1 += p[(b + 1) * (NG * FC1_OUT)];
            s2 += p[(b + 2) * (NG * FC1_OUT)];
            s3 += p[(b + 3) * (NG * FC1_OUT)];
        }
        g_t1[o] = (s0 + s1) + (s2 + s3);
    }
    grid_sync();

    // ---- P9: fc2 (blocks 0..15, one graph each) ----
    if (bid < NG) {
        for (int idx = t; idx < FC1_OUT; idx += NT)
            sh[idx] = fmaxf(g_t1[bid * FC1_OUT + idx] + fc1_b[idx], 0.0f);
        __syncthreads();
        if (t < FC2_OUT) {
            float acc = fc2_b[t];
#pragma unroll 8
            for (int k = 0; k < FC1_OUT; k++)
                acc = fmaf(sh[k], fc2_w[k * FC2_OUT + t], acc);
            out[bid * FC2_OUT + t] = acc;
        }
    }
}

extern "C" void kernel_launch(void* const* d_in, const int* in_sizes, int n_in,
                              void* d_out, int out_size) {
    mega_kernel<<<NB, NT>>>(
        d_in[1],                      // edge_index
        (const float*)d_in[0],        // x
        (const float*)d_in[2], (const float*)d_in[3],     // W1, b1
        (const float*)d_in[4], (const float*)d_in[5],     // W2, b2
        (const float*)d_in[6], (const float*)d_in[7],     // W3, b3
        (const float*)d_in[8], (const float*)d_in[9],     // fc1_w, fc1_b
        (const float*)d_in[10], (const float*)d_in[11],   // fc2_w, fc2_b
        (float*)d_out);
}

// round 9
// speedup vs baseline: 1.1126x; 1.0681x over previous
#include <cuda_runtime.h>
#include <cstdint>

static constexpr int NG      = 16;
static constexpr int NPG     = 4096;
static constexpr int NN      = NG * NPG;     // 65536 nodes
static constexpr int EE      = 1048576;      // edges
static constexpr int H       = 32;           // hidden
static constexpr int FC1_IN  = NPG * H;      // 131072
static constexpr int FC1_OUT = 256;
static constexpr int FC2_OUT = 64;
static constexpr int FC1_BLOCKS = 512;       // fc1 chunks of 256 inputs

static constexpr int NB = 888;               // 148 x 6 blocks, co-resident
static constexpr int NT = 256;
static constexpr int NWARP = NB * 8;         // 7104 warps

// -------- scratch (device globals; no allocation allowed) --------
// g_degi / g_cnt rely on being zero at kernel entry: zero at module load,
// re-zeroed at the tail of every graph_kernel run (behind a grid_sync).
__device__ int   g_degi[NN];
__device__ int   g_cnt [NN];
__device__ int   g_off [NN];          // block-local exclusive offsets
__device__ int   g_bsum[256];         // per-256-node-chunk bases (after scan2)
__device__ float g_dinv[NN];
__device__ int   g_eidx[EE];          // CSR: src indices grouped by dst
__device__ float g_h0 [NN * H];
__device__ float g_h1 [NN * H];
__device__ float g_act[NN * H];       // final pre-activated features for fc1
__device__ float g_t1p[FC1_BLOCKS * NG * FC1_OUT];   // fc1 partials (8 MB)
__device__ float g_t1 [NG * FC1_OUT];

// -------- software grid barrier (CG-style: bar.sync + release/acquire) ---
__device__ unsigned          g_bar_count;    // 0 at entry and after each use
__device__ volatile unsigned g_bar_gen;      // monotonically increasing

__device__ __forceinline__ void grid_sync() {
    __syncthreads();
    if (threadIdx.x == 0) {
        unsigned gen = g_bar_gen;
        __threadfence();                      // release (+ L1 invalidate)
        unsigned old = atomicAdd(&g_bar_count, 1u);
        if (old == (unsigned)NB - 1u) {
            g_bar_count = 0u;
            __threadfence();
            g_bar_gen = gen + 1u;             // release
        } else {
            while (g_bar_gen == gen) __nanosleep(64);
            __threadfence();                  // acquire
        }
    }
    __syncthreads();
}

// ---- packed f32x2 helpers (sm_103a) ----
__device__ __forceinline__ void fma2(unsigned long long& d,
                                     unsigned long long a,
                                     unsigned long long b) {
    asm("fma.rn.f32x2 %0, %1, %2, %0;" : "+l"(d) : "l"(a), "l"(b));
}
__device__ __forceinline__ unsigned long long pack2(float lo, float hi) {
    unsigned long long r;
    asm("mov.b64 %0, {%1, %2};" : "=l"(r) : "f"(lo), "f"(hi));
    return r;
}
__device__ __forceinline__ float unpack_sum(unsigned long long v) {
    float lo, hi;
    asm("mov.b64 {%0, %1}, %2;" : "=f"(lo), "=f"(hi) : "l"(v));
    return lo + hi;
}

// -------- fused CSR aggregation + activation (+ next matmul) phase -------
// LAYER 0: in g_h0, out g_h1, fused matmul
// LAYER 1: in g_h1, out g_h0, fused matmul
// LAYER 2: in g_h0, out g_act, activation only (feeds fc1)
template<int LAYER>
__device__ __forceinline__ void agg_phase(const float* __restrict__ W,
                                          const float* __restrict__ b,
                                          float* sh, int bid, int t) {
    const float* hs_in = (LAYER == 1) ? g_h1 : g_h0;
    float* outp = (LAYER == 0) ? g_h1 : (LAYER == 1) ? g_h0 : g_act;
    if (LAYER < 2)
        for (int i = t; i < H * H; i += NT) sh[i] = W[i];
    __syncthreads();
    int lane = t & 31, wp = t >> 5;
    float bl = b[lane];
    const float* hp = hs_in + lane;
    for (int n = bid * 8 + wp; n < NN; n += NWARP) {
        int start = g_off[n] + g_bsum[n >> 8];
        int end   = start + g_degi[n];
        float a0 = hs_in[n * H + lane];   // self-loop term
        float a1 = 0.f, a2 = 0.f, a3 = 0.f;
        for (int e0 = start; e0 < end; e0 += 32) {
            int cnt = min(32, end - e0);
            int my  = (lane < cnt) ? g_eidx[e0 + lane] : 0;
            int j = 0;
            for (; j + 4 <= cnt; j += 4) {
                int s0 = __shfl_sync(~0u, my, j);
                int s1 = __shfl_sync(~0u, my, j + 1);
                int s2 = __shfl_sync(~0u, my, j + 2);
                int s3 = __shfl_sync(~0u, my, j + 3);
                a0 += hp[s0 * H]; a1 += hp[s1 * H];
                a2 += hp[s2 * H]; a3 += hp[s3 * H];
            }
            for (; j < cnt; j++)
                a0 += hp[__shfl_sync(~0u, my, j) * H];
        }
        float dv = g_dinv[n];
        float agg = (a0 + a1) + (a2 + a3);
        float a = fmaxf(dv * agg + bl, 0.0f);
        if (LAYER == 2) { outp[n * H + lane] = a; continue; }
        float o = 0.0f;
#pragma unroll
        for (int k = 0; k < H; k++)
            o = fmaf(__shfl_sync(~0u, a, k), sh[k * H + lane], o);
        outp[n * H + lane] = o * dv;
    }
}

// ==================== kernel A: graph phases (persistent) ====================
__global__ __launch_bounds__(NT, 6)
void graph_kernel(const void* __restrict__ ei,
                  const float* __restrict__ x,
                  const float* __restrict__ W1, const float* __restrict__ b1,
                  const float* __restrict__ W2, const float* __restrict__ b2,
                  const float* __restrict__ W3, const float* __restrict__ b3) {
    __shared__ float sh[H * H];         // 4 KB
    __shared__ int   shi[8];

    const int t = threadIdx.x, bid = blockIdx.x;
    const int lane = t & 31, wp = t >> 5;

    // dtype detect, per block (int64 buffers: odd 32-bit words all zero)
    const unsigned* w32 = (const unsigned*)ei;
    const int is64 = __syncthreads_and(w32[2 * t + 1] == 0u);

    // ---- P0: degree histogram (counters pre-zeroed invariant) ----
    if (is64) {
        const long long* p = (const long long*)ei + EE;
        for (int e = bid * NT + t; e < EE; e += NB * NT)
            atomicAdd(&g_degi[(int)p[e]], 1);
    } else {
        const int* p = (const int*)ei + EE;
        for (int e = bid * NT + t; e < EE; e += NB * NT)
            atomicAdd(&g_degi[p[e]], 1);
    }
    grid_sync();

    // ---- P1: per-256-chunk exclusive scan; emits dinv + chunk totals ----
    if (bid < 256) {
        int i = bid * 256 + t;
        int v = g_degi[i];
        g_dinv[i] = rsqrtf((float)v + 1.0f);
        int s = v;
#pragma unroll
        for (int off = 1; off < 32; off <<= 1) {
            int xx = __shfl_up_sync(~0u, s, off);
            if (lane >= off) s += xx;
        }
        if (lane == 31) shi[wp] = s;
        __syncthreads();
        if (wp == 0) {
            int orig = (lane < 8) ? shi[lane] : 0;
            int ws = orig;
#pragma unroll
            for (int off = 1; off < 8; off <<= 1) {
                int xx = __shfl_up_sync(~0u, ws, off);
                if (lane >= off) ws += xx;
            }
            if (lane < 8) shi[lane] = ws - orig;
        }
        __syncthreads();
        g_off[i] = s - v + shi[wp];
        if (t == 255) g_bsum[bid] = s + shi[7];
    }
    grid_sync();

    // ---- P2: exclusive scan of 256 chunk totals (block 0) ----
    if (bid == 0) {
        int v = g_bsum[t];
        int s = v;
#pragma unroll
        for (int off = 1; off < 32; off <<= 1) {
            int xx = __shfl_up_sync(~0u, s, off);
            if (lane >= off) s += xx;
        }
        if (lane == 31) shi[wp] = s;
        __syncthreads();
        if (wp == 0) {
            int orig = (lane < 8) ? shi[lane] : 0;
            int ws = orig;
#pragma unroll
            for (int off = 1; off < 8; off <<= 1) {
                int xx = __shfl_up_sync(~0u, ws, off);
                if (lane >= off) ws += xx;
            }
            if (lane < 8) shi[lane] = ws - orig;
        }
        __syncthreads();
        g_bsum[t] = s - v + shi[wp];
    }
    grid_sync();

    // ---- P3: CSR fill + layer-1 transform ----
    {
        for (int i = t; i < 16 * 32; i += NT) sh[i] = W1[i];
        __syncthreads();
        if (is64) {
            const long long* p = (const long long*)ei;
            for (int e = bid * NT + t; e < EE; e += NB * NT) {
                int s = (int)p[e];
                int d = (int)p[EE + e];
                g_eidx[g_off[d] + g_bsum[d >> 8] + atomicAdd(&g_cnt[d], 1)] = s;
            }
        } else {
            const int* p = (const int*)ei;
            for (int e = bid * NT + t; e < EE; e += NB * NT) {
                int s = p[e];
                int d = p[EE + e];
                g_eidx[g_off[d] + g_bsum[d >> 8] + atomicAdd(&g_cnt[d], 1)] = s;
            }
        }
        for (int n = bid * 8 + wp; n < NN; n += NWARP) {
            float a = (lane < 16) ? x[n * 16 + lane] : 0.0f;
            float o = 0.0f;
#pragma unroll
            for (int k = 0; k < 16; k++)
                o = fmaf(__shfl_sync(~0u, a, k), sh[k * 32 + lane], o);
            g_h0[n * 32 + lane] = o * g_dinv[n];
        }
    }
    grid_sync();

    // ---- P4..P6: three aggregation layers ----
    agg_phase<0>(W2, b1, sh, bid, t);
    grid_sync();
    agg_phase<1>(W3, b2, sh, bid, t);
    grid_sync();
    agg_phase<2>(nullptr, b3, sh, bid, t);
    grid_sync();   // REQUIRED: agg_phase<2> of other blocks still reads g_degi
                   // (round-8 bug: zeroing raced with readers)

    // ---- tail: restore counter invariant ----
    for (int i = bid * NT + t; i < NN; i += NB * NT) {
        g_cnt[i]  = 0;
        g_degi[i] = 0;
    }
}

// ==================== kernel B: fc1 partials ====================
__global__ void fc1_kernel(const float* __restrict__ fc1_w) {
    __shared__ float a_s[NG * 256];              // 16 KB, [g][i]
    int t  = threadIdx.x;                         // output column 0..255
    int i0 = blockIdx.x * 256;

    for (int idx = t; idx < NG * 64; idx += 256) {   // 16g x 64 float4
        int g  = idx >> 6;
        int i4 = idx & 63;
        float4 v = *reinterpret_cast<const float4*>(g_act + g * FC1_IN + i0 + i4 * 4);
        *reinterpret_cast<float4*>(&a_s[g * 256 + i4 * 4]) = v;
    }
    __syncthreads();

    unsigned long long r2[NG];
#pragma unroll
    for (int g = 0; g < NG; g++) r2[g] = 0ull;

    for (int i = 0; i < 256; i += 4) {
        int base = (i0 + i) * FC1_OUT + t;
        unsigned long long wA = pack2(fc1_w[base],               fc1_w[base +     FC1_OUT]);
        unsigned long long wB = pack2(fc1_w[base + 2 * FC1_OUT], fc1_w[base + 3 * FC1_OUT]);
#pragma unroll
        for (int g = 0; g < NG; g++) {
            unsigned long long aA =
                *reinterpret_cast<const unsigned long long*>(&a_s[g * 256 + i]);
            unsigned long long aB =
                *reinterpret_cast<const unsigned long long*>(&a_s[g * 256 + i + 2]);
            fma2(r2[g], aA, wA);
            fma2(r2[g], aB, wB);
        }
    }
    float* outp = g_t1p + blockIdx.x * (NG * FC1_OUT);
#pragma unroll
    for (int g = 0; g < NG; g++)
        outp[g * FC1_OUT + t] = unpack_sum(r2[g]);
}

// ==================== kernel C: reduce fc1 partials ====================
// 128 blocks x 256 threads; block owns 32 of 4096 outputs; 8-way b-split.
__global__ void reduce_t1_kernel() {
    __shared__ float sred[256];
    int t = threadIdx.x;
    int ol   = t & 31;                 // output within block's 32
    int part = t >> 5;                 // 0..7, slice of the 512 partials
    int o = blockIdx.x * 32 + ol;
    float s0 = 0.f, s1 = 0.f;
    const float* p = g_t1p + o;
#pragma unroll 4
    for (int i = 0; i < 64; i += 2) {
        int b = part * 64 + i;
        s0 += p[(b + 0) * (NG * FC1_OUT)];
        s1 += p[(b + 1) * (NG * FC1_OUT)];
    }
    sred[ol * 8 + part] = s0 + s1;
    __syncthreads();
    if (t < 32) {
        float acc = 0.f;
#pragma unroll
        for (int k = 0; k < 8; k++) acc += sred[t * 8 + k];
        g_t1[blockIdx.x * 32 + t] = acc;
    }
}

// ==================== kernel D: fc2 ====================
__global__ void fc2_kernel(const float* __restrict__ fc1_b,
                           const float* __restrict__ fc2_w,
                           const float* __restrict__ fc2_b,
                           float* __restrict__ out) {
    __shared__ float s[FC1_OUT];
    int t = threadIdx.x, g = blockIdx.x;
    s[t] = fmaxf(g_t1[g * FC1_OUT + t] + fc1_b[t], 0.0f);
    __syncthreads();
    if (t < FC2_OUT) {
        float acc = fc2_b[t];
#pragma unroll 8
        for (int k = 0; k < FC1_OUT; k++)
            acc = fmaf(s[k], fc2_w[k * FC2_OUT + t], acc);
        out[g * FC2_OUT + t] = acc;
    }
}

extern "C" void kernel_launch(void* const* d_in, const int* in_sizes, int n_in,
                              void* d_out, int out_size) {
    graph_kernel<<<NB, NT>>>(
        d_in[1],                      // edge_index
        (const float*)d_in[0],        // x
        (const float*)d_in[2], (const float*)d_in[3],     // W1, b1
        (const float*)d_in[4], (const float*)d_in[5],     // W2, b2
        (const float*)d_in[6], (const float*)d_in[7]);    // W3, b3
    fc1_kernel<<<FC1_BLOCKS, 256>>>((const float*)d_in[8]);
    reduce_t1_kernel<<<128, 256>>>();
    fc2_kernel<<<NG, FC1_OUT>>>((const float*)d_in[9],
                                (const float*)d_in[10],
                                (const float*)d_in[11],
                                (float*)d_out);
}

// round 10
// speedup vs baseline: 1.1778x; 1.0586x over previous
#include <cuda_runtime.h>
#include <cstdint>

static constexpr int NG      = 16;
static constexpr int NPG     = 4096;
static constexpr int NN      = NG * NPG;     // 65536 nodes
static constexpr int EE      = 1048576;      // edges
static constexpr int H       = 32;           // hidden
static constexpr int FC1_IN  = NPG * H;      // 131072
static constexpr int FC1_OUT = 256;
static constexpr int FC2_OUT = 64;
static constexpr int FC1_BLOCKS = 512;       // fc1 chunks of 256 inputs

static constexpr int NB = 888;               // 148 x 6 blocks, co-resident
static constexpr int NT = 256;
static constexpr int NWARP = NB * 8;         // 7104 warps

// -------- scratch (device globals; no allocation allowed) --------
__device__ int   g_degi[NN];
__device__ int   g_cnt [NN];
__device__ int   g_off [NN];          // block-local exclusive offsets
__device__ int   g_bsum[256];         // per-256-node-chunk bases (after scan2)
__device__ float g_dinv[NN];
__device__ int   g_eidx[EE];          // CSR: src indices grouped by dst
__device__ float g_h0 [NN * H];
__device__ float g_h1 [NN * H];
__device__ float g_act[NN * H];       // final pre-activated features for fc1
__device__ float g_t1p[FC1_BLOCKS * NG * FC1_OUT];   // fc1 partials (8 MB)

// -------- software grid barrier (CG-style: bar.sync + release/acquire) ---
__device__ unsigned          g_bar_count;    // 0 at entry and after each use
__device__ volatile unsigned g_bar_gen;      // monotonically increasing

__device__ __forceinline__ void grid_sync() {
    __syncthreads();
    if (threadIdx.x == 0) {
        unsigned gen = g_bar_gen;
        __threadfence();                      // release
        unsigned old = atomicAdd(&g_bar_count, 1u);
        if (old == (unsigned)NB - 1u) {
            g_bar_count = 0u;
            __threadfence();
            g_bar_gen = gen + 1u;             // release
        } else {
            while (g_bar_gen == gen) __nanosleep(64);
            __threadfence();                  // acquire
        }
    }
    __syncthreads();
}

// ---- packed f32x2 helpers (sm_103a) ----
__device__ __forceinline__ void fma2(unsigned long long& d,
                                     unsigned long long a,
                                     unsigned long long b) {
    asm("fma.rn.f32x2 %0, %1, %2, %0;" : "+l"(d) : "l"(a), "l"(b));
}
__device__ __forceinline__ unsigned long long pack2(float lo, float hi) {
    unsigned long long r;
    asm("mov.b64 %0, {%1, %2};" : "=l"(r) : "f"(lo), "f"(hi));
    return r;
}
__device__ __forceinline__ float unpack_sum(unsigned long long v) {
    float lo, hi;
    asm("mov.b64 {%0, %1}, %2;" : "=f"(lo), "=f"(hi) : "l"(v));
    return lo + hi;
}

// ==================== kernels 0/1: zero counters ====================
__global__ void zero_degi_kernel() {
    g_degi[blockIdx.x * 256 + threadIdx.x] = 0;
}
__global__ void zero_cnt_kernel() {
    g_cnt[blockIdx.x * 256 + threadIdx.x] = 0;
}

// ==================== kernel 2: build (persistent) ====================
// P0 histogram -> P1/P2 scans -> P3 CSR fill + layer-1 transform
__global__ __launch_bounds__(NT, 6)
void build_kernel(const void* __restrict__ ei,
                  const float* __restrict__ x,
                  const float* __restrict__ W1) {
    __shared__ float sh[16 * 32];
    __shared__ int   shi[8];

    const int t = threadIdx.x, bid = blockIdx.x;
    const int lane = t & 31, wp = t >> 5;

    // dtype detect, per block (int64 buffers: odd 32-bit words all zero)
    const unsigned* w32 = (const unsigned*)ei;
    const int is64 = __syncthreads_and(w32[2 * t + 1] == 0u);

    // ---- P0: degree histogram ----
    if (is64) {
        const long long* p = (const long long*)ei + EE;
        for (int e = bid * NT + t; e < EE; e += NB * NT)
            atomicAdd(&g_degi[(int)__ldcs(&p[e])], 1);
    } else {
        const int* p = (const int*)ei + EE;
        for (int e = bid * NT + t; e < EE; e += NB * NT)
            atomicAdd(&g_degi[__ldcs(&p[e])], 1);
    }
    grid_sync();

    // ---- P1: per-256-chunk exclusive scan; emits dinv + chunk totals ----
    if (bid < 256) {
        int i = bid * 256 + t;
        int v = g_degi[i];
        g_dinv[i] = rsqrtf((float)v + 1.0f);
        int s = v;
#pragma unroll
        for (int off = 1; off < 32; off <<= 1) {
            int xx = __shfl_up_sync(~0u, s, off);
            if (lane >= off) s += xx;
        }
        if (lane == 31) shi[wp] = s;
        __syncthreads();
        if (wp == 0) {
            int orig = (lane < 8) ? shi[lane] : 0;
            int ws = orig;
#pragma unroll
            for (int off = 1; off < 8; off <<= 1) {
                int xx = __shfl_up_sync(~0u, ws, off);
                if (lane >= off) ws += xx;
            }
            if (lane < 8) shi[lane] = ws - orig;
        }
        __syncthreads();
        g_off[i] = s - v + shi[wp];
        if (t == 255) g_bsum[bid] = s + shi[7];
    }
    grid_sync();

    // ---- P2: exclusive scan of 256 chunk totals (block 0) ----
    if (bid == 0) {
        int v = g_bsum[t];
        int s = v;
#pragma unroll
        for (int off = 1; off < 32; off <<= 1) {
            int xx = __shfl_up_sync(~0u, s, off);
            if (lane >= off) s += xx;
        }
        if (lane == 31) shi[wp] = s;
        __syncthreads();
        if (wp == 0) {
            int orig = (lane < 8) ? shi[lane] : 0;
            int ws = orig;
#pragma unroll
            for (int off = 1; off < 8; off <<= 1) {
                int xx = __shfl_up_sync(~0u, ws, off);
                if (lane >= off) ws += xx;
            }
            if (lane < 8) shi[lane] = ws - orig;
        }
        __syncthreads();
        g_bsum[t] = s - v + shi[wp];
    }
    grid_sync();

    // ---- P3: CSR fill + layer-1 transform ----
    for (int i = t; i < 16 * 32; i += NT) sh[i] = W1[i];
    __syncthreads();
    if (is64) {
        const long long* p = (const long long*)ei;
        for (int e = bid * NT + t; e < EE; e += NB * NT) {
            int s = (int)__ldcs(&p[e]);
            int d = (int)__ldcs(&p[EE + e]);
            g_eidx[g_off[d] + g_bsum[d >> 8] + atomicAdd(&g_cnt[d], 1)] = s;
        }
    } else {
        const int* p = (const int*)ei;
        for (int e = bid * NT + t; e < EE; e += NB * NT) {
            int s = __ldcs(&p[e]);
            int d = __ldcs(&p[EE + e]);
            g_eidx[g_off[d] + g_bsum[d >> 8] + atomicAdd(&g_cnt[d], 1)] = s;
        }
    }
    for (int n = bid * 8 + wp; n < NN; n += NWARP) {
        float a = (lane < 16) ? x[n * 16 + lane] : 0.0f;
        float o = 0.0f;
#pragma unroll
        for (int k = 0; k < 16; k++)
            o = fmaf(__shfl_sync(~0u, a, k), sh[k * 32 + lane], o);
        g_h0[n * 32 + lane] = o * g_dinv[n];
    }
}

// ==================== kernel 3: agg_all (persistent) ====================
// LAYER 0: in g_h0, out g_h1, fused matmul
// LAYER 1: in g_h1, out g_h0, fused matmul
// LAYER 2: in g_h0, out g_act, activation only (feeds fc1)
// Index fetch: uniform LDG broadcast (one wavefront, L1-hot) — no shfl.
template<int LAYER>
__device__ __forceinline__ void agg_phase(const float* __restrict__ W,
                                          const float* __restrict__ b,
                                          float* sh, int bid, int t) {
    const float* hs_in = (LAYER == 1) ? g_h1 : g_h0;
    float* outp = (LAYER == 0) ? g_h1 : (LAYER == 1) ? g_h0 : g_act;
    if (LAYER < 2)
        for (int i = t; i < H * H; i += NT) sh[i] = W[i];
    __syncthreads();
    int lane = t & 31, wp = t >> 5;
    float bl = b[lane];
    const float* hp = hs_in + lane;
    for (int n = bid * 8 + wp; n < NN; n += NWARP) {
        int start = g_off[n] + g_bsum[n >> 8];
        int end   = start + g_degi[n];
        float a0 = hs_in[n * H + lane];   // self-loop term
        float a1 = 0.f, a2 = 0.f, a3 = 0.f;
        int e = start;
        for (; e + 4 <= end; e += 4) {
            int s0 = g_eidx[e + 0];
            int s1 = g_eidx[e + 1];
            int s2 = g_eidx[e + 2];
            int s3 = g_eidx[e + 3];
            a0 += hp[s0 * H]; a1 += hp[s1 * H];
            a2 += hp[s2 * H]; a3 += hp[s3 * H];
        }
        for (; e < end; e++)
            a0 += hp[g_eidx[e] * H];
        float dv = g_dinv[n];
        float agg = (a0 + a1) + (a2 + a3);
        float a = fmaxf(dv * agg + bl, 0.0f);
        if (LAYER == 2) { outp[n * H + lane] = a; continue; }
        float o = 0.0f;
#pragma unroll
        for (int k = 0; k < H; k++)
            o = fmaf(__shfl_sync(~0u, a, k), sh[k * H + lane], o);
        outp[n * H + lane] = o * dv;
    }
}

__global__ __launch_bounds__(NT, 6)
void agg_all_kernel(const float* __restrict__ W2, const float* __restrict__ b1,
                    const float* __restrict__ W3, const float* __restrict__ b2,
                    const float* __restrict__ b3) {
    __shared__ float sh[H * H];
    const int t = threadIdx.x, bid = blockIdx.x;
    agg_phase<0>(W2, b1, sh, bid, t);
    grid_sync();
    agg_phase<1>(W3, b2, sh, bid, t);
    grid_sync();
    agg_phase<2>(nullptr, b3, sh, bid, t);
}

// ==================== kernel 4: fc1 partials ====================
__global__ void fc1_kernel(const float* __restrict__ fc1_w) {
    __shared__ float a_s[NG * 256];              // 16 KB, [g][i]
    int t  = threadIdx.x;                         // output column 0..255
    int i0 = blockIdx.x * 256;

    for (int idx = t; idx < NG * 64; idx += 256) {   // 16g x 64 float4
        int g  = idx >> 6;
        int i4 = idx & 63;
        float4 v = *reinterpret_cast<const float4*>(g_act + g * FC1_IN + i0 + i4 * 4);
        *reinterpret_cast<float4*>(&a_s[g * 256 + i4 * 4]) = v;
    }
    __syncthreads();

    unsigned long long r2[NG];
#pragma unroll
    for (int g = 0; g < NG; g++) r2[g] = 0ull;

    for (int i = 0; i < 256; i += 4) {
        int base = (i0 + i) * FC1_OUT + t;
        unsigned long long wA = pack2(fc1_w[base],               fc1_w[base +     FC1_OUT]);
        unsigned long long wB = pack2(fc1_w[base + 2 * FC1_OUT], fc1_w[base + 3 * FC1_OUT]);
#pragma unroll
        for (int g = 0; g < NG; g++) {
            unsigned long long aA =
                *reinterpret_cast<const unsigned long long*>(&a_s[g * 256 + i]);
            unsigned long long aB =
                *reinterpret_cast<const unsigned long long*>(&a_s[g * 256 + i + 2]);
            fma2(r2[g], aA, wA);
            fma2(r2[g], aB, wB);
        }
    }
    float* outp = g_t1p + blockIdx.x * (NG * FC1_OUT);
#pragma unroll
    for (int g = 0; g < NG; g++)
        outp[g * FC1_OUT + t] = unpack_sum(r2[g]);
}

// ==================== kernel 5: tail = reduce partials + fc2 ====================
// grid 16 (one block per graph) x 1024 threads.
__global__ void tail_kernel(const float* __restrict__ fc1_b,
                            const float* __restrict__ fc2_w,
                            const float* __restrict__ fc2_b,
                            float* __restrict__ out) {
    __shared__ float sp[1024];
    __shared__ float s[FC1_OUT];
    int g = blockIdx.x, t = threadIdx.x;
    int o = t & 255, q = t >> 8;                 // q in 0..3: slice of 512 partials

    const float* p = g_t1p + g * FC1_OUT + o;
    float acc = 0.0f;
#pragma unroll 8
    for (int i = 0; i < 128; i++)
        acc += p[(q * 128 + i) * (NG * FC1_OUT)];
    sp[q * 256 + o] = acc;
    __syncthreads();
    if (t < FC1_OUT)
        s[t] = fmaxf(sp[t] + sp[256 + t] + sp[512 + t] + sp[768 + t] + fc1_b[t], 0.0f);
    __syncthreads();

    // fc2: 64 outputs x 16 threads each (16 k per thread), shfl reduce
    int oo = t >> 4, qq = t & 15;
    float a2 = 0.0f;
#pragma unroll
    for (int k = qq * 16; k < qq * 16 + 16; k++)
        a2 = fmaf(s[k], fc2_w[k * FC2_OUT + oo], a2);
    a2 += __shfl_down_sync(~0u, a2, 8, 16);
    a2 += __shfl_down_sync(~0u, a2, 4, 16);
    a2 += __shfl_down_sync(~0u, a2, 2, 16);
    a2 += __shfl_down_sync(~0u, a2, 1, 16);
    if (qq == 0)
        out[g * FC2_OUT + oo] = a2 + fc2_b[oo];
}

extern "C" void kernel_launch(void* const* d_in, const int* in_sizes, int n_in,
                              void* d_out, int out_size) {
    zero_degi_kernel<<<NN / 256, 256>>>();
    zero_cnt_kernel<<<NN / 256, 256>>>();
    build_kernel<<<NB, NT>>>(d_in[1], (const float*)d_in[0], (const float*)d_in[2]);
    agg_all_kernel<<<NB, NT>>>((const float*)d_in[4], (const float*)d_in[3],
                               (const float*)d_in[6], (const float*)d_in[5],
                               (const float*)d_in[7]);
    fc1_kernel<<<FC1_BLOCKS, 256>>>((const float*)d_in[8]);
    tail_kernel<<<NG, 1024>>>((const float*)d_in[9],
                              (const float*)d_in[10],
                              (const float*)d_in[11],
                              (float*)d_out);
}

// round 11
// speedup vs baseline: 1.1872x; 1.0079x over previous
#include <cuda_runtime.h>
#include <cstdint>

static constexpr int NG      = 16;
static constexpr int NPG     = 4096;
static constexpr int NN      = NG * NPG;     // 65536 nodes
static constexpr int EE      = 1048576;      // edges
static constexpr int H       = 32;           // hidden
static constexpr int FC1_IN  = NPG * H;      // 131072
static constexpr int FC1_OUT = 256;
static constexpr int FC2_OUT = 64;
static constexpr int FC1_BLOCKS = 512;       // fc1 chunks of 256 inputs

static constexpr int NB = 888;               // persistent grid (build kernel)
static constexpr int NT = 256;
static constexpr int NWARP = NB * 8;

// agg kernel: 5 blocks/SM (reg headroom for unroll-8 gather)
static constexpr int NBA = 740;              // 148 x 5
static constexpr int NWARPA = NBA * 8;

// -------- scratch (device globals; no allocation allowed) --------
__device__ int   g_degi[NN];
__device__ int   g_cnt [NN];
__device__ int   g_off [NN];          // block-local exclusive offsets
__device__ int   g_bsum[256];         // per-256-node-chunk bases (after scan2)
__device__ float g_dinv[NN];
__device__ int   g_eidx[EE];          // CSR: src indices grouped by dst
__device__ float g_h0 [NN * H];
__device__ float g_h1 [NN * H];
__device__ float g_act[NN * H];       // final pre-activated features for fc1
__device__ float g_t1p[FC1_BLOCKS * NG * FC1_OUT];   // fc1 partials (8 MB)

// -------- software grid barriers (separate for each persistent kernel) ---
__device__ unsigned          g_bar_count;
__device__ volatile unsigned g_bar_gen;
__device__ unsigned          g_bar_count2;
__device__ volatile unsigned g_bar_gen2;

template<int N>
__device__ __forceinline__ void grid_sync_n(unsigned* cnt, volatile unsigned* gen_p) {
    __syncthreads();
    if (threadIdx.x == 0) {
        unsigned gen = *gen_p;
        __threadfence();                      // release
        unsigned old = atomicAdd(cnt, 1u);
        if (old == (unsigned)N - 1u) {
            *cnt = 0u;
            __threadfence();
            *gen_p = gen + 1u;                // release
        } else {
            while (*gen_p == gen) __nanosleep(64);
            __threadfence();                  // acquire
        }
    }
    __syncthreads();
}

// ---- packed f32x2 helpers (sm_103a) ----
__device__ __forceinline__ void fma2(unsigned long long& d,
                                     unsigned long long a,
                                     unsigned long long b) {
    asm("fma.rn.f32x2 %0, %1, %2, %0;" : "+l"(d) : "l"(a), "l"(b));
}
__device__ __forceinline__ unsigned long long pack2(float lo, float hi) {
    unsigned long long r;
    asm("mov.b64 %0, {%1, %2};" : "=l"(r) : "f"(lo), "f"(hi));
    return r;
}
__device__ __forceinline__ float unpack_sum(unsigned long long v) {
    float lo, hi;
    asm("mov.b64 {%0, %1}, %2;" : "=f"(lo), "=f"(hi) : "l"(v));
    return lo + hi;
}

// ==================== kernel 0: zero counters ====================
__global__ void zero_kernel() {
    int i = blockIdx.x * 256 + threadIdx.x;
    g_degi[i] = 0;
    g_cnt[i]  = 0;
}

// ==================== kernel 1: build (persistent) ====================
// P0 histogram -> P1/P2 scans -> P3 CSR fill + layer-1 transform
__global__ __launch_bounds__(NT, 6)
void build_kernel(const void* __restrict__ ei,
                  const float* __restrict__ x,
                  const float* __restrict__ W1) {
    __shared__ float sh[16 * 32];
    __shared__ int   shi[8];

    const int t = threadIdx.x, bid = blockIdx.x;
    const int lane = t & 31, wp = t >> 5;

    // dtype detect, per block (int64 buffers: odd 32-bit words all zero)
    const unsigned* w32 = (const unsigned*)ei;
    const int is64 = __syncthreads_and(w32[2 * t + 1] == 0u);

    // ---- P0: degree histogram ----
    if (is64) {
        const long long* p = (const long long*)ei + EE;
        for (int e = bid * NT + t; e < EE; e += NB * NT)
            atomicAdd(&g_degi[(int)__ldcs(&p[e])], 1);
    } else {
        const int* p = (const int*)ei + EE;
        for (int e = bid * NT + t; e < EE; e += NB * NT)
            atomicAdd(&g_degi[__ldcs(&p[e])], 1);
    }
    grid_sync_n<NB>(&g_bar_count, &g_bar_gen);

    // ---- P1: per-256-chunk exclusive scan; emits dinv + chunk totals ----
    if (bid < 256) {
        int i = bid * 256 + t;
        int v = g_degi[i];
        g_dinv[i] = rsqrtf((float)v + 1.0f);
        int s = v;
#pragma unroll
        for (int off = 1; off < 32; off <<= 1) {
            int xx = __shfl_up_sync(~0u, s, off);
            if (lane >= off) s += xx;
        }
        if (lane == 31) shi[wp] = s;
        __syncthreads();
        if (wp == 0) {
            int orig = (lane < 8) ? shi[lane] : 0;
            int ws = orig;
#pragma unroll
            for (int off = 1; off < 8; off <<= 1) {
                int xx = __shfl_up_sync(~0u, ws, off);
                if (lane >= off) ws += xx;
            }
            if (lane < 8) shi[lane] = ws - orig;
        }
        __syncthreads();
        g_off[i] = s - v + shi[wp];
        if (t == 255) g_bsum[bid] = s + shi[7];
    }
    grid_sync_n<NB>(&g_bar_count, &g_bar_gen);

    // ---- P2: exclusive scan of 256 chunk totals (block 0) ----
    if (bid == 0) {
        int v = g_bsum[t];
        int s = v;
#pragma unroll
        for (int off = 1; off < 32; off <<= 1) {
            int xx = __shfl_up_sync(~0u, s, off);
            if (lane >= off) s += xx;
        }
        if (lane == 31) shi[wp] = s;
        __syncthreads();
        if (wp == 0) {
            int orig = (lane < 8) ? shi[lane] : 0;
            int ws = orig;
#pragma unroll
            for (int off = 1; off < 8; off <<= 1) {
                int xx = __shfl_up_sync(~0u, ws, off);
                if (lane >= off) ws += xx;
            }
            if (lane < 8) shi[lane] = ws - orig;
        }
        __syncthreads();
        g_bsum[t] = s - v + shi[wp];
    }
    grid_sync_n<NB>(&g_bar_count, &g_bar_gen);

    // ---- P3: CSR fill + layer-1 transform ----
    for (int i = t; i < 16 * 32; i += NT) sh[i] = W1[i];
    __syncthreads();
    if (is64) {
        const long long* p = (const long long*)ei;
        for (int e = bid * NT + t; e < EE; e += NB * NT) {
            int s = (int)__ldcs(&p[e]);
            int d = (int)__ldcs(&p[EE + e]);
            g_eidx[g_off[d] + g_bsum[d >> 8] + atomicAdd(&g_cnt[d], 1)] = s;
        }
    } else {
        const int* p = (const int*)ei;
        for (int e = bid * NT + t; e < EE; e += NB * NT) {
            int s = __ldcs(&p[e]);
            int d = __ldcs(&p[EE + e]);
            g_eidx[g_off[d] + g_bsum[d >> 8] + atomicAdd(&g_cnt[d], 1)] = s;
        }
    }
    for (int n = bid * 8 + wp; n < NN; n += NWARP) {
        float a = (lane < 16) ? x[n * 16 + lane] : 0.0f;
        float o = 0.0f;
#pragma unroll
        for (int k = 0; k < 16; k++)
            o = fmaf(__shfl_sync(~0u, a, k), sh[k * 32 + lane], o);
        g_h0[n * 32 + lane] = o * g_dinv[n];
    }
}

// ==================== kernel 2: agg_all (persistent) ====================
// LAYER 0: in g_h0, out g_h1, fused matmul
// LAYER 1: in g_h1, out g_h0, fused matmul
// LAYER 2: in g_h0, out g_act, activation only (feeds fc1)
// Index fetch: int4 uniform loads (4 edges/wavefront); feature MLP = 8.
template<int LAYER>
__device__ __forceinline__ void agg_phase(const float* __restrict__ W,
                                          const float* __restrict__ b,
                                          float* sh, int bid, int t) {
    const float* hs_in = (LAYER == 1) ? g_h1 : g_h0;
    float* outp = (LAYER == 0) ? g_h1 : (LAYER == 1) ? g_h0 : g_act;
    if (LAYER < 2)
        for (int i = t; i < H * H; i += NT) sh[i] = W[i];
    __syncthreads();
    int lane = t & 31, wp = t >> 5;
    float bl = b[lane];
    const float* hp = hs_in + lane;
    for (int n = bid * 8 + wp; n < NN; n += NWARPA) {
        int start = g_off[n] + g_bsum[n >> 8];
        int end   = start + g_degi[n];
        float a0 = hs_in[n * H + lane];   // self-loop term
        float a1 = 0.f, a2 = 0.f, a3 = 0.f;
        float a4 = 0.f, a5 = 0.f, a6 = 0.f, a7 = 0.f;
        int e = start;
        while ((e & 3) && e < end)                    // align to int4
            a0 += hp[g_eidx[e++] * H];
        for (; e + 8 <= end; e += 8) {
            int4 i0 = *reinterpret_cast<const int4*>(&g_eidx[e]);
            int4 i1 = *reinterpret_cast<const int4*>(&g_eidx[e + 4]);
            a0 += hp[i0.x * H]; a1 += hp[i0.y * H];
            a2 += hp[i0.z * H]; a3 += hp[i0.w * H];
            a4 += hp[i1.x * H]; a5 += hp[i1.y * H];
            a6 += hp[i1.z * H]; a7 += hp[i1.w * H];
        }
        if (e + 4 <= end) {
            int4 i0 = *reinterpret_cast<const int4*>(&g_eidx[e]);
            a0 += hp[i0.x * H]; a1 += hp[i0.y * H];
            a2 += hp[i0.z * H]; a3 += hp[i0.w * H];
            e += 4;
        }
        for (; e < end; e++)
            a0 += hp[g_eidx[e] * H];
        float dv = g_dinv[n];
        float agg = ((a0 + a1) + (a2 + a3)) + ((a4 + a5) + (a6 + a7));
        float a = fmaxf(dv * agg + bl, 0.0f);
        if (LAYER == 2) { outp[n * H + lane] = a; continue; }
        float o = 0.0f;
#pragma unroll
        for (int k = 0; k < H; k++)
            o = fmaf(__shfl_sync(~0u, a, k), sh[k * H + lane], o);
        outp[n * H + lane] = o * dv;
    }
}

__global__ __launch_bounds__(NT, 5)
void agg_all_kernel(const float* __restrict__ W2, const float* __restrict__ b1,
                    const float* __restrict__ W3, const float* __restrict__ b2,
                    const float* __restrict__ b3) {
    __shared__ float sh[H * H];
    const int t = threadIdx.x, bid = blockIdx.x;
    agg_phase<0>(W2, b1, sh, bid, t);
    grid_sync_n<NBA>(&g_bar_count2, &g_bar_gen2);
    agg_phase<1>(W3, b2, sh, bid, t);
    grid_sync_n<NBA>(&g_bar_count2, &g_bar_gen2);
    agg_phase<2>(nullptr, b3, sh, bid, t);
}

// ==================== kernel 3: fc1 partials ====================
__global__ void fc1_kernel(const float* __restrict__ fc1_w) {
    __shared__ float a_s[NG * 256];              // 16 KB, [g][i]
    int t  = threadIdx.x;                         // output column 0..255
    int i0 = blockIdx.x * 256;

    for (int idx = t; idx < NG * 64; idx += 256) {   // 16g x 64 float4
        int g  = idx >> 6;
        int i4 = idx & 63;
        float4 v = *reinterpret_cast<const float4*>(g_act + g * FC1_IN + i0 + i4 * 4);
        *reinterpret_cast<float4*>(&a_s[g * 256 + i4 * 4]) = v;
    }
    __syncthreads();

    unsigned long long r2[NG];
#pragma unroll
    for (int g = 0; g < NG; g++) r2[g] = 0ull;

    for (int i = 0; i < 256; i += 4) {
        int base = (i0 + i) * FC1_OUT + t;
        // streamed once: evict-streaming keeps fc1_w out of L2's hot set
        float w0 = __ldcs(&fc1_w[base]);
        float w1 = __ldcs(&fc1_w[base +     FC1_OUT]);
        float w2 = __ldcs(&fc1_w[base + 2 * FC1_OUT]);
        float w3 = __ldcs(&fc1_w[base + 3 * FC1_OUT]);
        unsigned long long wA = pack2(w0, w1);
        unsigned long long wB = pack2(w2, w3);
#pragma unroll
        for (int g = 0; g < NG; g++) {
            unsigned long long aA =
                *reinterpret_cast<const unsigned long long*>(&a_s[g * 256 + i]);
            unsigned long long aB =
                *reinterpret_cast<const unsigned long long*>(&a_s[g * 256 + i + 2]);
            fma2(r2[g], aA, wA);
            fma2(r2[g], aB, wB);
        }
    }
    float* outp = g_t1p + blockIdx.x * (NG * FC1_OUT);
#pragma unroll
    for (int g = 0; g < NG; g++)
        outp[g * FC1_OUT + t] = unpack_sum(r2[g]);
}

// ==================== kernel 4: tail = reduce partials + fc2 ====================
// grid 16 (one block per graph) x 1024 threads.
__global__ void tail_kernel(const float* __restrict__ fc1_b,
                            const float* __restrict__ fc2_w,
                            const float* __restrict__ fc2_b,
                            float* __restrict__ out) {
    __shared__ float sp[1024];
    __shared__ float s[FC1_OUT];
    int g = blockIdx.x, t = threadIdx.x;
    int o = t & 255, q = t >> 8;                 // q in 0..3: slice of 512 partials

    const float* p = g_t1p + g * FC1_OUT + o;
    float acc = 0.0f;
#pragma unroll 8
    for (int i = 0; i < 128; i++)
        acc += p[(q * 128 + i) * (NG * FC1_OUT)];
    sp[q * 256 + o] = acc;
    __syncthreads();
    if (t < FC1_OUT)
        s[t] = fmaxf(sp[t] + sp[256 + t] + sp[512 + t] + sp[768 + t] + fc1_b[t], 0.0f);
    __syncthreads();

    // fc2: 64 outputs x 16 threads each (16 k per thread), shfl reduce
    int oo = t >> 4, qq = t & 15;
    float a2 = 0.0f;
#pragma unroll
    for (int k = qq * 16; k < qq * 16 + 16; k++)
        a2 = fmaf(s[k], fc2_w[k * FC2_OUT + oo], a2);
    a2 += __shfl_down_sync(~0u, a2, 8, 16);
    a2 += __shfl_down_sync(~0u, a2, 4, 16);
    a2 += __shfl_down_sync(~0u, a2, 2, 16);
    a2 += __shfl_down_sync(~0u, a2, 1, 16);
    if (qq == 0)
        out[g * FC2_OUT + oo] = a2 + fc2_b[oo];
}

extern "C" void kernel_launch(void* const* d_in, const int* in_sizes, int n_in,
                              void* d_out, int out_size) {
    zero_kernel<<<NN / 256, 256>>>();
    build_kernel<<<NB, NT>>>(d_in[1], (const float*)d_in[0], (const float*)d_in[2]);
    agg_all_kernel<<<NBA, NT>>>((const float*)d_in[4], (const float*)d_in[3],
                                (const float*)d_in[6], (const float*)d_in[5],
                                (const float*)d_in[7]);
    fc1_kernel<<<FC1_BLOCKS, 256>>>((const float*)d_in[8]);
    tail_kernel<<<NG, 1024>>>((const float*)d_in[9],
                              (const float*)d_in[10],
                              (const float*)d_in[11],
                              (float*)d_out);
}